// round 14
// baseline (speedup 1.0000x reference)
#include <cuda_runtime.h>
#include <cuda_fp16.h>
#include <stdint.h>
#include <string.h>
#include <math.h>

// ---------------------------------------------------------------------------
// Problem constants
// ---------------------------------------------------------------------------
#define BB 4096
#define NN 19
#define EE 342
#define ET 361
#define FF 256
#define HH 512
#define OO 256
#define MM (BB * NN)      // 77824, divisible by 128

// ---------------------------------------------------------------------------
// Scratch (device globals)
// ---------------------------------------------------------------------------
__device__ __half g_A [(size_t)MM * HH];     // activations fp16
__device__ __half g_H [(size_t)MM * HH];     // GEMM output fp16
__device__ __half g_W [4][HH * HH];          // transposed fp16 weights [N,K]

// ---------------------------------------------------------------------------
// Helpers
// ---------------------------------------------------------------------------
__device__ __forceinline__ uint32_t smem_u32(const void* p) {
    uint32_t a;
    asm("{ .reg .u64 t; cvta.to.shared.u64 t, %1; cvt.u32.u64 %0, t; }"
        : "=r"(a) : "l"(p));
    return a;
}
#define SWZ64(o) ((o) ^ (((o) >> 3) & 0x30))

__device__ __forceinline__ void cp16(uint32_t s, const void* g) {
    asm volatile("cp.async.cg.shared.global [%0], [%1], 16;" :: "r"(s), "l"(g));
}

__device__ __forceinline__ unsigned long long packf2(float x, float y) {
    unsigned long long u;
    asm("mov.b64 %0, {%1, %2};" : "=l"(u) : "f"(x), "f"(y));
    return u;
}
__device__ __forceinline__ float2 unpackf2(unsigned long long u) {
    float x, y;
    asm("mov.b64 {%0, %1}, %2;" : "=f"(x), "=f"(y) : "l"(u));
    return make_float2(x, y);
}
__device__ __forceinline__ void fma2(unsigned long long& acc,
                                     unsigned long long a, unsigned long long b) {
    asm("fma.rn.f32x2 %0, %1, %2, %0;" : "+l"(acc) : "l"(a), "l"(b));
}

// ---------------------------------------------------------------------------
// Setup kernels
// ---------------------------------------------------------------------------
__global__ void cvt_x_kernel(const float* __restrict__ x,
                             __half* __restrict__ A, size_t n) {
    size_t i = (size_t)blockIdx.x * 256 + threadIdx.x;
    if (i < n) A[i] = __float2half_rn(x[i]);
}

__global__ void cvt_w_kernel(const float* __restrict__ W,
                             __half* __restrict__ Wt, int K, int N) {
    int i = blockIdx.x * 256 + threadIdx.x;
    if (i < K * N) {
        int n = i / K, k = i % K;
        Wt[i] = __float2half_rn(W[(size_t)k * N + n]);
    }
}

// ---------------------------------------------------------------------------
// fp16 single-pass GEMM (unchanged from round 13)
// ---------------------------------------------------------------------------
#define GEMM_STAGE 16384
#define GEMM_SMEM  (4 * GEMM_STAGE)

template <int K, int NT>
__global__ void __launch_bounds__(256, 2)
gemm_mma(const __half* __restrict__ A, const __half* __restrict__ B,
         __half* __restrict__ Hout)
{
    extern __shared__ char smem[];
    const uint32_t sb = smem_u32(smem);
    const int tid  = threadIdx.x;
    const int wid  = tid >> 5;
    const int lane = tid & 31;
    const int bm = blockIdx.y * 128;
    const int bn = blockIdx.x * 128;
    const int wm = wid & 1;
    const int wn = wid >> 1;

    constexpr int NCH = K / 32;

    auto issue = [&](int ch) {
        const uint32_t st = sb + (uint32_t)(ch & 3) * GEMM_STAGE;
        const int kb = ch * 32;
#pragma unroll
        for (int i = 0; i < 2; i++) {
            int u = tid + i * 256;
            int rr = u >> 2, cc = u & 3;
            uint32_t so = SWZ64((uint32_t)(rr * 64 + cc * 16));
            cp16(st + so,         A + (size_t)(bm + rr) * K + kb + cc * 8);
            cp16(st + 8192u + so, B + (size_t)(bn + rr) * K + kb + cc * 8);
        }
    };

    float acc[4][4][4] = {};

    issue(0);
    asm volatile("cp.async.commit_group;" ::: "memory");
    issue(1);
    asm volatile("cp.async.commit_group;" ::: "memory");
    issue(2);
    asm volatile("cp.async.commit_group;" ::: "memory");

    for (int ch = 0; ch < NCH; ch++) {
        if (ch + 3 < NCH) {
            asm volatile("cp.async.wait_group 2;" ::: "memory");
            __syncthreads();
            issue(ch + 3);
            asm volatile("cp.async.commit_group;" ::: "memory");
        } else {
            asm volatile("cp.async.wait_group 0;" ::: "memory");
            __syncthreads();
        }

        const uint32_t st = sb + (uint32_t)(ch & 3) * GEMM_STAGE;
        const uint32_t sA = st;
        const uint32_t sB = st + 8192u;
#pragma unroll
        for (int kk = 0; kk < 2; kk++) {
            uint32_t b[8];
#pragma unroll
            for (int g = 0; g < 2; g++) {
                int n = wn * 32 + g * 16 + ((lane >> 4) * 8) + (lane & 7);
                int c = kk * 2 + ((lane >> 3) & 1);
                uint32_t so = SWZ64((uint32_t)(n * 64 + c * 16));
                asm volatile(
                    "ldmatrix.sync.aligned.m8n8.x4.shared.b16 {%0,%1,%2,%3}, [%4];"
                    : "=r"(b[g * 4 + 0]), "=r"(b[g * 4 + 1]),
                      "=r"(b[g * 4 + 2]), "=r"(b[g * 4 + 3])
                    : "r"(sB + so));
            }
#pragma unroll
            for (int mt = 0; mt < 4; mt++) {
                uint32_t a[4];
                int m = wm * 64 + mt * 16 + (lane & 15);
                int c = kk * 2 + (lane >> 4);
                uint32_t so = SWZ64((uint32_t)(m * 64 + c * 16));
                asm volatile(
                    "ldmatrix.sync.aligned.m8n8.x4.shared.b16 {%0,%1,%2,%3}, [%4];"
                    : "=r"(a[0]), "=r"(a[1]), "=r"(a[2]), "=r"(a[3])
                    : "r"(sA + so));
#pragma unroll
                for (int nt = 0; nt < 4; nt++) {
                    float* d = acc[mt][nt];
                    asm volatile(
                        "mma.sync.aligned.m16n8k16.row.col.f32.f16.f16.f32 "
                        "{%0,%1,%2,%3}, {%4,%5,%6,%7}, {%8,%9}, {%0,%1,%2,%3};"
                        : "+f"(d[0]), "+f"(d[1]), "+f"(d[2]), "+f"(d[3])
                        : "r"(a[0]), "r"(a[1]), "r"(a[2]), "r"(a[3]),
                          "r"(b[nt * 2]), "r"(b[nt * 2 + 1]));
                }
            }
        }
    }

#pragma unroll
    for (int mt = 0; mt < 4; mt++) {
        int row0 = bm + wm * 64 + mt * 16 + (lane >> 2);
#pragma unroll
        for (int nt = 0; nt < 4; nt++) {
            int col = bn + wn * 32 + nt * 8 + (lane & 3) * 2;
            float* d = acc[mt][nt];
            *(__half2*)(Hout + (size_t)row0 * NT + col) =
                __floats2half2_rn(d[0], d[1]);
            *(__half2*)(Hout + (size_t)(row0 + 8) * NT + col) =
                __floats2half2_rn(d[2], d[3]);
        }
    }
}

// ---------------------------------------------------------------------------
// Attention + aggregation, register-resident h (2 channels/thread).
// C channels, T = C/2 threads.  Dense alpha duplicated as float2 in smem,
// aggregation via packed fma.rn.f32x2.
// ---------------------------------------------------------------------------
template <int T>
__device__ __forceinline__ void alpha_edges(
    const int* __restrict__ ei, const float* als, const float* ald,
    float* nsum, float* ebuf, float* alphaM, int t)
{
    for (int e = t; e < ET; e += T) {
        int se = (e < EE) ? ei[e] : (e - EE);
        int de = (e < EE) ? ei[EE + e] : (e - EE);
        float z = als[se] + ald[de];
        float lg = (z >= 0.f) ? z : 0.2f * z;
        float ex = __expf(lg);
        ebuf[e] = ex;
        atomicAdd(&nsum[de], ex);
    }
    __syncthreads();
    if (t < NN) nsum[t] = 1.f / nsum[t];
    __syncthreads();
    for (int e = t; e < ET; e += T) {
        int se = (e < EE) ? ei[e] : (e - EE);
        int de = (e < EE) ? ei[EE + e] : (e - EE);
        atomicAdd(&alphaM[de * NN + se], ebuf[e] * nsum[de]);
    }
    __syncthreads();
}

template <int C, bool RELU>
__global__ void __launch_bounds__(C / 2) gat_agg_h(
    const __half* __restrict__ H, const int* __restrict__ ei,
    const float* __restrict__ a_s, const float* __restrict__ a_d,
    const float* __restrict__ bias,
    __half* __restrict__ Oh)
{
    constexpr int T = C / 2;
    __shared__ float als[NN], ald[NN], nsum[NN];
    __shared__ float ebuf[ET];
    __shared__ float alphaM[NN * NN];
    __shared__ alignas(8) float2 alphaD[NN * NN];

    const int t = threadIdx.x;
    const int lane = t & 31;
    const size_t gbase = (size_t)blockIdx.x * NN * C;

    if (t < NN) { als[t] = 0.f; ald[t] = 0.f; nsum[t] = 0.f; }
    for (int i = t; i < NN * NN; i += T) alphaM[i] = 0.f;

    // register-resident h: 2 channels per thread, packed f32x2
    unsigned long long h2[NN];
    {
        const __half2* H2 = (const __half2*)(H + gbase);
#pragma unroll
        for (int s = 0; s < NN; s++) {
            float2 f = __half22float2(H2[(size_t)s * T + t]);
            h2[s] = packf2(f.x, f.y);
        }
    }
    const float as0 = __ldg(a_s + 2 * t), as1 = __ldg(a_s + 2 * t + 1);
    const float ad0 = __ldg(a_d + 2 * t), ad1 = __ldg(a_d + 2 * t + 1);
    __syncthreads();

    // logits: per-node warp reduction + smem atomics
#pragma unroll
    for (int n = 0; n < NN; n++) {
        float2 f = unpackf2(h2[n]);
        float s = f.x * as0 + f.y * as1;
        float d = f.x * ad0 + f.y * ad1;
#pragma unroll
        for (int o = 16; o; o >>= 1) {
            s += __shfl_xor_sync(0xffffffffu, s, o);
            d += __shfl_xor_sync(0xffffffffu, d, o);
        }
        if (lane == 0) { atomicAdd(&als[n], s); atomicAdd(&ald[n], d); }
    }
    __syncthreads();

    alpha_edges<T>(ei, als, ald, nsum, ebuf, alphaM, t);

    // duplicate-pack alpha for LDS.64 broadcast
    for (int i = t; i < NN * NN; i += T) {
        float a = alphaM[i];
        alphaD[i] = make_float2(a, a);
    }
    __syncthreads();

    const unsigned long long bc = packf2(__ldg(bias + 2 * t), __ldg(bias + 2 * t + 1));
    __half2* O2 = (__half2*)(Oh + gbase);
#pragma unroll
    for (int n = 0; n < NN; n++) {
        unsigned long long acc = bc;
        const unsigned long long* ap = (const unsigned long long*)&alphaD[n * NN];
#pragma unroll
        for (int s = 0; s < NN; s++) fma2(acc, ap[s], h2[s]);
        float2 v = unpackf2(acc);
        if (RELU) { v.x = fmaxf(v.x, 0.f); v.y = fmaxf(v.y, 0.f); }
        O2[(size_t)n * T + t] = __floats2half2_rn(v.x, v.y);
    }
}

// Final layer: aggregation (no relu) + fused head, fully register-resident.
//   scores[n] = sigmoid( v[n] . (sum_m ws[m] v[m]) + bs )
__global__ void __launch_bounds__(OO / 2) gat_final(
    const __half* __restrict__ H, const int* __restrict__ ei,
    const float* __restrict__ a_s, const float* __restrict__ a_d,
    const float* __restrict__ bias, float* __restrict__ outp,
    const float* __restrict__ ws, const float* __restrict__ bsc)
{
    constexpr int C = OO;
    constexpr int T = C / 2;
    __shared__ float als[NN], ald[NN], nsum[NN];
    __shared__ float ebuf[ET];
    __shared__ float alphaM[NN * NN];
    __shared__ alignas(8) float2 alphaD[NN * NN];
    __shared__ float sbuf[NN];

    const int t = threadIdx.x;
    const int lane = t & 31;
    const size_t gbase = (size_t)blockIdx.x * NN * C;

    if (t < NN) { als[t] = 0.f; ald[t] = 0.f; nsum[t] = 0.f; sbuf[t] = 0.f; }
    for (int i = t; i < NN * NN; i += T) alphaM[i] = 0.f;

    unsigned long long h2[NN];
    {
        const __half2* H2 = (const __half2*)(H + gbase);
#pragma unroll
        for (int s = 0; s < NN; s++) {
            float2 f = __half22float2(H2[(size_t)s * T + t]);
            h2[s] = packf2(f.x, f.y);
        }
    }
    const float as0 = __ldg(a_s + 2 * t), as1 = __ldg(a_s + 2 * t + 1);
    const float ad0 = __ldg(a_d + 2 * t), ad1 = __ldg(a_d + 2 * t + 1);
    __syncthreads();

#pragma unroll
    for (int n = 0; n < NN; n++) {
        float2 f = unpackf2(h2[n]);
        float s = f.x * as0 + f.y * as1;
        float d = f.x * ad0 + f.y * ad1;
#pragma unroll
        for (int o = 16; o; o >>= 1) {
            s += __shfl_xor_sync(0xffffffffu, s, o);
            d += __shfl_xor_sync(0xffffffffu, d, o);
        }
        if (lane == 0) { atomicAdd(&als[n], s); atomicAdd(&ald[n], d); }
    }
    __syncthreads();

    alpha_edges<T>(ei, als, ald, nsum, ebuf, alphaM, t);

    for (int i = t; i < NN * NN; i += T) {
        float a = alphaM[i];
        alphaD[i] = make_float2(a, a);
    }
    __syncthreads();

    // aggregated outputs v[n] (2 channels per thread, kept in registers)
    const unsigned long long bc = packf2(__ldg(bias + 2 * t), __ldg(bias + 2 * t + 1));
    float2 v[NN];
#pragma unroll
    for (int n = 0; n < NN; n++) {
        unsigned long long acc = bc;
        const unsigned long long* ap = (const unsigned long long*)&alphaD[n * NN];
#pragma unroll
        for (int s = 0; s < NN; s++) fma2(acc, ap[s], h2[s]);
        v[n] = unpackf2(acc);
    }

    // p = sum_n ws[n] * v[n]  (per-thread, 2 channels)
    float2 p = make_float2(0.f, 0.f);
#pragma unroll
    for (int n = 0; n < NN; n++) {
        float w = __ldg(ws + n);
        p.x += w * v[n].x;
        p.y += w * v[n].y;
    }

    // scores: sc[n] = sum_c v[n][c] * p[c]  -> warp reduce + smem atomic
#pragma unroll
    for (int n = 0; n < NN; n++) {
        float s = v[n].x * p.x + v[n].y * p.y;
#pragma unroll
        for (int o = 16; o; o >>= 1) s += __shfl_xor_sync(0xffffffffu, s, o);
        if (lane == 0) atomicAdd(&sbuf[n], s);
    }
    __syncthreads();
    if (t < NN)
        outp[(size_t)blockIdx.x * NN + t] = 1.f / (1.f + __expf(-(sbuf[t] + bsc[0])));
}

// ---------------------------------------------------------------------------
// Launch.  ncu captures launch index 3 -> layer-1 GEMM placed there.
// ---------------------------------------------------------------------------
extern "C" void kernel_launch(void* const* d_in, const int* in_sizes, int n_in,
                              void* d_out, int out_size)
{
    (void)in_sizes; (void)n_in; (void)out_size;
    const float* x   = (const float*)d_in[0];
    const int*   ei  = (const int*)  d_in[1];
    const float* W1  = (const float*)d_in[3];
    const float* as1 = (const float*)d_in[4];
    const float* ad1 = (const float*)d_in[5];
    const float* b1  = (const float*)d_in[6];
    const float* W2  = (const float*)d_in[7];
    const float* as2 = (const float*)d_in[8];
    const float* ad2 = (const float*)d_in[9];
    const float* b2  = (const float*)d_in[10];
    const float* W3  = (const float*)d_in[11];
    const float* as3 = (const float*)d_in[12];
    const float* ad3 = (const float*)d_in[13];
    const float* b3  = (const float*)d_in[14];
    const float* W4  = (const float*)d_in[15];
    const float* as4 = (const float*)d_in[16];
    const float* ad4 = (const float*)d_in[17];
    const float* b4  = (const float*)d_in[18];
    const float* ws  = (const float*)d_in[19];
    const float* bs  = (const float*)d_in[20];
    float* out = (float*)d_out;

    __half *A, *Hb, *W;
    cudaGetSymbolAddress((void**)&A,  g_A);
    cudaGetSymbolAddress((void**)&Hb, g_H);
    cudaGetSymbolAddress((void**)&W,  g_W);

    cudaFuncSetAttribute(gemm_mma<FF, HH>, cudaFuncAttributeMaxDynamicSharedMemorySize, GEMM_SMEM);
    cudaFuncSetAttribute(gemm_mma<HH, HH>, cudaFuncAttributeMaxDynamicSharedMemorySize, GEMM_SMEM);
    cudaFuncSetAttribute(gemm_mma<HH, OO>, cudaFuncAttributeMaxDynamicSharedMemorySize, GEMM_SMEM);

    __half* W0  = W + 0 * (size_t)(HH * HH);
    __half* W1t = W + 1 * (size_t)(HH * HH);
    __half* W2t = W + 2 * (size_t)(HH * HH);
    __half* W3t = W + 3 * (size_t)(HH * HH);

    const dim3 g2(HH / 128, MM / 128);   // (4, 608)
    const dim3 g1(OO / 128, MM / 128);   // (2, 608)

    // idx 0-2: setup needed by layer-1 GEMM
    cvt_w_kernel<<<(FF * HH + 255) / 256, 256>>>(W1, W0, FF, HH);                 // 0
    cvt_x_kernel<<<(MM * FF + 255) / 256, 256>>>(x, A, (size_t)MM * FF);          // 1
    cvt_w_kernel<<<(HH * HH + 255) / 256, 256>>>(W2, W1t, HH, HH);                // 2

    // idx 3: Layer 1 GEMM — ncu capture target
    gemm_mma<FF, HH><<<g2, 256, GEMM_SMEM>>>(A, W0, Hb);                           // 3

    cvt_w_kernel<<<(HH * HH + 255) / 256, 256>>>(W3, W2t, HH, HH);                // 4
    cvt_w_kernel<<<(HH * OO + 255) / 256, 256>>>(W4, W3t, HH, OO);                // 5
    gat_agg_h<HH, true><<<BB, HH / 2>>>(Hb, ei, as1, ad1, b1, A);
    // Layer 2
    gemm_mma<HH, HH><<<g2, 256, GEMM_SMEM>>>(A, W1t, Hb);
    gat_agg_h<HH, true><<<BB, HH / 2>>>(Hb, ei, as2, ad2, b2, A);
    // Layer 3
    gemm_mma<HH, HH><<<g2, 256, GEMM_SMEM>>>(A, W2t, Hb);
    gat_agg_h<HH, true><<<BB, HH / 2>>>(Hb, ei, as3, ad3, b3, A);
    // Layer 4 + fused head
    gemm_mma<HH, OO><<<g1, 256, GEMM_SMEM>>>(A, W3t, Hb);
    gat_final<<<BB, OO / 2>>>(Hb, ei, as4, ad4, b4, out, ws, bs);
}

// round 15
// speedup vs baseline: 1.0448x; 1.0448x over previous
#include <cuda_runtime.h>
#include <cuda_fp16.h>
#include <stdint.h>
#include <math.h>

// ---------------------------------------------------------------------------
// Problem constants
// ---------------------------------------------------------------------------
#define BB 4096
#define NN 19
#define EE 342
#define ET 361
#define FF 256
#define HH 512
#define OO 256
#define MM (BB * NN)      // 77824 = 304 * 256

// ---------------------------------------------------------------------------
// Scratch (device globals)
// ---------------------------------------------------------------------------
__device__ __half g_A [(size_t)MM * HH];     // activations fp16
__device__ __half g_H [(size_t)MM * HH];     // GEMM output fp16
__device__ __half g_W [4][HH * HH];          // transposed fp16 weights [N,K]

// ---------------------------------------------------------------------------
// Helpers
// ---------------------------------------------------------------------------
__device__ __forceinline__ uint32_t smem_u32(const void* p) {
    uint32_t a;
    asm("{ .reg .u64 t; cvta.to.shared.u64 t, %1; cvt.u32.u64 %0, t; }"
        : "=r"(a) : "l"(p));
    return a;
}
// 128-byte-row swizzle
#define SWZ(o) ((o) ^ (((o) >> 3) & 0x70))

__device__ __forceinline__ void cp16(uint32_t s, const void* g) {
    asm volatile("cp.async.cg.shared.global [%0], [%1], 16;" :: "r"(s), "l"(g));
}

// ---------------------------------------------------------------------------
// Setup kernels
// ---------------------------------------------------------------------------
__global__ void cvt_x_kernel(const float* __restrict__ x,
                             __half* __restrict__ A, size_t n) {
    size_t i = (size_t)blockIdx.x * 256 + threadIdx.x;
    if (i < n) A[i] = __float2half_rn(x[i]);
}

__global__ void cvt_w_kernel(const float* __restrict__ W,
                             __half* __restrict__ Wt, int K, int N) {
    int i = blockIdx.x * 256 + threadIdx.x;
    if (i < K * N) {
        int n = i / K, k = i % K;
        Wt[i] = __float2half_rn(W[(size_t)k * N + n]);
    }
}

// ---------------------------------------------------------------------------
// fp16 single-pass GEMM:  H[M,NT] = A @ W,  fp32 accumulators, fp16 output.
// A: [M,K] fp16 row-major.  W: [NT,K] (n-major, K contiguous).
// CTA tile 256x128, 8 warps (4M x 2N), warp tile 64x64.
// K-chunks of 64 (128B rows, SW128), 3-stage cp.async pipeline,
// stage = A(32K) | B(16K) = 48KB;  3 stages = 144KB/CTA (1 CTA/SM).
// Per kk step: 8 LDSM.x4 feed 32 MMAs (crossbar ~= tensor pipe).
// ---------------------------------------------------------------------------
#define GEMM_STAGE 49152
#define GEMM_SMEM  (3 * GEMM_STAGE)

template <int K, int NT>
__global__ void __launch_bounds__(256, 1)
gemm_mma(const __half* __restrict__ A, const __half* __restrict__ B,
         __half* __restrict__ Hout)
{
    extern __shared__ char smem[];
    const uint32_t sb = smem_u32(smem);
    const int tid  = threadIdx.x;
    const int wid  = tid >> 5;
    const int lane = tid & 31;
    const int bm = blockIdx.y * 256;
    const int bn = blockIdx.x * 128;
    const int wm = wid >> 1;       // 0..3  (M quarters of 64)
    const int wn = wid & 1;        // 0..1  (N halves of 64)

    constexpr int NCH = K / 64;    // K-chunks

    auto issue = [&](int ch) {
        const uint32_t st = sb + (uint32_t)(ch % 3) * GEMM_STAGE;
        const int kb = ch * 64;
        // A: 256 rows x 128B = 2048 units; B: 128 rows x 128B = 1024 units
#pragma unroll
        for (int i = 0; i < 12; i++) {
            int u = tid + i * 256;
            if (u < 2048) {
                int r = u >> 3, c = u & 7;
                cp16(st + SWZ((uint32_t)(r * 128 + c * 16)),
                     A + (size_t)(bm + r) * K + kb + c * 8);
            } else {
                int v = u - 2048;
                int r = v >> 3, c = v & 7;
                cp16(st + 32768u + SWZ((uint32_t)(r * 128 + c * 16)),
                     B + (size_t)(bn + r) * K + kb + c * 8);
            }
        }
    };

    float acc[4][8][4] = {};

    issue(0);
    asm volatile("cp.async.commit_group;" ::: "memory");
    issue(1);
    asm volatile("cp.async.commit_group;" ::: "memory");

    for (int ch = 0; ch < NCH; ch++) {
        if (ch + 2 < NCH) {
            asm volatile("cp.async.wait_group 1;" ::: "memory");
            __syncthreads();
            issue(ch + 2);
            asm volatile("cp.async.commit_group;" ::: "memory");
        } else if (ch + 1 < NCH) {
            asm volatile("cp.async.wait_group 1;" ::: "memory");
            __syncthreads();
        } else {
            asm volatile("cp.async.wait_group 0;" ::: "memory");
            __syncthreads();
        }

        const uint32_t st = sb + (uint32_t)(ch % 3) * GEMM_STAGE;
        const uint32_t sA = st;
        const uint32_t sB = st + 32768u;
#pragma unroll
        for (int kk = 0; kk < 4; kk++) {
            // B fragments: warp's 64 cols -> 8 n8-tiles -> 16 regs
            uint32_t b[16];
#pragma unroll
            for (int g = 0; g < 4; g++) {
                int n = wn * 64 + g * 16 + ((lane >> 4) * 8) + (lane & 7);
                int c = kk * 2 + ((lane >> 3) & 1);
                uint32_t so = SWZ((uint32_t)(n * 128 + c * 16));
                asm volatile(
                    "ldmatrix.sync.aligned.m8n8.x4.shared.b16 {%0,%1,%2,%3}, [%4];"
                    : "=r"(b[g * 4 + 0]), "=r"(b[g * 4 + 1]),
                      "=r"(b[g * 4 + 2]), "=r"(b[g * 4 + 3])
                    : "r"(sB + so));
            }
#pragma unroll
            for (int mt = 0; mt < 4; mt++) {
                uint32_t a[4];
                int m = wm * 64 + mt * 16 + (lane & 15);
                int c = kk * 2 + (lane >> 4);
                uint32_t so = SWZ((uint32_t)(m * 128 + c * 16));
                asm volatile(
                    "ldmatrix.sync.aligned.m8n8.x4.shared.b16 {%0,%1,%2,%3}, [%4];"
                    : "=r"(a[0]), "=r"(a[1]), "=r"(a[2]), "=r"(a[3])
                    : "r"(sA + so));
#pragma unroll
                for (int nt = 0; nt < 8; nt++) {
                    float* d = acc[mt][nt];
                    asm volatile(
                        "mma.sync.aligned.m16n8k16.row.col.f32.f16.f16.f32 "
                        "{%0,%1,%2,%3}, {%4,%5,%6,%7}, {%8,%9}, {%0,%1,%2,%3};"
                        : "+f"(d[0]), "+f"(d[1]), "+f"(d[2]), "+f"(d[3])
                        : "r"(a[0]), "r"(a[1]), "r"(a[2]), "r"(a[3]),
                          "r"(b[nt * 2]), "r"(b[nt * 2 + 1]));
                }
            }
        }
    }

    // Epilogue: fp16 stores (half2).
#pragma unroll
    for (int mt = 0; mt < 4; mt++) {
        int row0 = bm + wm * 64 + mt * 16 + (lane >> 2);
#pragma unroll
        for (int nt = 0; nt < 8; nt++) {
            int col = bn + wn * 64 + nt * 8 + (lane & 3) * 2;
            float* d = acc[mt][nt];
            *(__half2*)(Hout + (size_t)row0 * NT + col) =
                __floats2half2_rn(d[0], d[1]);
            *(__half2*)(Hout + (size_t)(row0 + 8) * NT + col) =
                __floats2half2_rn(d[2], d[3]);
        }
    }
}

// ---------------------------------------------------------------------------
// Attention + aggregation (round-13 version). One CTA per graph, C threads.
// Reads fp16 H into fp32 smem tile; softmax without max-subtraction.
// ---------------------------------------------------------------------------
template <int C>
__device__ __forceinline__ void load_h_tile(const __half* __restrict__ H,
                                            size_t gbase, float* hs, int t) {
    const uint4* H8 = (const uint4*)(H + gbase);
    for (int i = t; i < NN * C / 8; i += C) {
        uint4 u = H8[i];
        const __half2* hp = (const __half2*)&u;
        float* o = hs + i * 8;
        float2 f0 = __half22float2(hp[0]);
        float2 f1 = __half22float2(hp[1]);
        float2 f2 = __half22float2(hp[2]);
        float2 f3 = __half22float2(hp[3]);
        o[0] = f0.x; o[1] = f0.y; o[2] = f1.x; o[3] = f1.y;
        o[4] = f2.x; o[5] = f2.y; o[6] = f3.x; o[7] = f3.y;
    }
}

template <int C>
__device__ __forceinline__ void attn_alpha(
    const float* __restrict__ hs, const int* __restrict__ ei,
    const float* __restrict__ a_s, const float* __restrict__ a_d,
    float* als, float* ald, float* nsum, float* ebuf, float* alphaM, int t)
{
    {
        const int w = t >> 5, lane = t & 31, NW = C / 32;
        for (int n = w; n < NN; n += NW) {
            float s = 0.f, d = 0.f;
#pragma unroll
            for (int j = 0; j < C / 32; j++) {
                float h = hs[n * C + lane + 32 * j];
                s += h * __ldg(a_s + lane + 32 * j);
                d += h * __ldg(a_d + lane + 32 * j);
            }
#pragma unroll
            for (int o = 16; o; o >>= 1) {
                s += __shfl_xor_sync(0xffffffffu, s, o);
                d += __shfl_xor_sync(0xffffffffu, d, o);
            }
            if (lane == 0) { als[n] = s; ald[n] = d; }
        }
    }
    __syncthreads();
    for (int e = t; e < ET; e += C) {
        int se = (e < EE) ? ei[e] : (e - EE);
        int de = (e < EE) ? ei[EE + e] : (e - EE);
        float z = als[se] + ald[de];
        float lg = (z >= 0.f) ? z : 0.2f * z;
        float ex = __expf(lg);
        ebuf[e] = ex;
        atomicAdd(&nsum[de], ex);
    }
    __syncthreads();
    if (t < NN) nsum[t] = 1.f / nsum[t];
    __syncthreads();
    for (int e = t; e < ET; e += C) {
        int se = (e < EE) ? ei[e] : (e - EE);
        int de = (e < EE) ? ei[EE + e] : (e - EE);
        atomicAdd(&alphaM[de * NN + se], ebuf[e] * nsum[de]);
    }
    __syncthreads();
}

template <int C, bool RELU>
__global__ void __launch_bounds__(C) gat_agg_h(
    const __half* __restrict__ H, const int* __restrict__ ei,
    const float* __restrict__ a_s, const float* __restrict__ a_d,
    const float* __restrict__ bias,
    __half* __restrict__ Oh)
{
    __shared__ alignas(16) float hs[NN * C];
    __shared__ float als[NN], ald[NN], nsum[NN];
    __shared__ float ebuf[ET];
    __shared__ float alphaM[NN * NN];

    const int t = threadIdx.x;
    const size_t gbase = (size_t)blockIdx.x * NN * C;

    if (t < NN) nsum[t] = 0.f;
    for (int i = t; i < NN * NN; i += C) alphaM[i] = 0.f;
    load_h_tile<C>(H, gbase, hs, t);
    __syncthreads();

    attn_alpha<C>(hs, ei, a_s, a_d, als, ald, nsum, ebuf, alphaM, t);

    float hreg[NN];
#pragma unroll
    for (int s = 0; s < NN; s++) hreg[s] = hs[s * C + t];
    const float bc = bias[t];
#pragma unroll
    for (int n = 0; n < NN; n++) {
        float acc = 0.f;
#pragma unroll
        for (int s = 0; s < NN; s++) acc += alphaM[n * NN + s] * hreg[s];
        float v = acc + bc;
        if (RELU) v = fmaxf(v, 0.f);
        Oh[gbase + (size_t)n * C + t] = __float2half_rn(v);
    }
}

// Final layer: aggregation (no relu) + fused head
__global__ void __launch_bounds__(OO) gat_final(
    const __half* __restrict__ H, const int* __restrict__ ei,
    const float* __restrict__ a_s, const float* __restrict__ a_d,
    const float* __restrict__ bias, float* __restrict__ outp,
    const float* __restrict__ ws, const float* __restrict__ bsc)
{
    constexpr int C = OO;
    __shared__ alignas(16) float hs[NN * C];
    __shared__ float als[NN], ald[NN], nsum[NN];
    __shared__ float ebuf[ET];
    __shared__ float alphaM[NN * NN];
    __shared__ alignas(16) float outbuf[NN * C];
    __shared__ float pbuf[C];

    const int t = threadIdx.x;
    const size_t gbase = (size_t)blockIdx.x * NN * C;

    if (t < NN) nsum[t] = 0.f;
    for (int i = t; i < NN * NN; i += C) alphaM[i] = 0.f;
    load_h_tile<C>(H, gbase, hs, t);
    __syncthreads();

    attn_alpha<C>(hs, ei, a_s, a_d, als, ald, nsum, ebuf, alphaM, t);

    float hreg[NN];
#pragma unroll
    for (int s = 0; s < NN; s++) hreg[s] = hs[s * C + t];
    const float bc = bias[t];
#pragma unroll
    for (int n = 0; n < NN; n++) {
        float acc = 0.f;
#pragma unroll
        for (int s = 0; s < NN; s++) acc += alphaM[n * NN + s] * hreg[s];
        outbuf[n * C + t] = acc + bc;
    }
    __syncthreads();

    {
        float pv = 0.f;
#pragma unroll
        for (int n = 0; n < NN; n++) pv += ws[n] * outbuf[n * C + t];
        pbuf[t] = pv;
    }
    __syncthreads();
    {
        const int w = t >> 5, lane = t & 31, NW = C / 32;
        const float bv = bsc[0];
        for (int n = w; n < NN; n += NW) {
            float s = 0.f;
#pragma unroll
            for (int j = 0; j < C / 32; j++)
                s += outbuf[n * C + lane + 32 * j] * pbuf[lane + 32 * j];
#pragma unroll
            for (int o = 16; o; o >>= 1)
                s += __shfl_xor_sync(0xffffffffu, s, o);
            if (lane == 0)
                outp[(size_t)blockIdx.x * NN + n] = 1.f / (1.f + __expf(-(s + bv)));
        }
    }
}

// ---------------------------------------------------------------------------
// Launch.  ncu captures launch index 3 -> layer-1 GEMM placed there.
// ---------------------------------------------------------------------------
extern "C" void kernel_launch(void* const* d_in, const int* in_sizes, int n_in,
                              void* d_out, int out_size)
{
    (void)in_sizes; (void)n_in; (void)out_size;
    const float* x   = (const float*)d_in[0];
    const int*   ei  = (const int*)  d_in[1];
    const float* W1  = (const float*)d_in[3];
    const float* as1 = (const float*)d_in[4];
    const float* ad1 = (const float*)d_in[5];
    const float* b1  = (const float*)d_in[6];
    const float* W2  = (const float*)d_in[7];
    const float* as2 = (const float*)d_in[8];
    const float* ad2 = (const float*)d_in[9];
    const float* b2  = (const float*)d_in[10];
    const float* W3  = (const float*)d_in[11];
    const float* as3 = (const float*)d_in[12];
    const float* ad3 = (const float*)d_in[13];
    const float* b3  = (const float*)d_in[14];
    const float* W4  = (const float*)d_in[15];
    const float* as4 = (const float*)d_in[16];
    const float* ad4 = (const float*)d_in[17];
    const float* b4  = (const float*)d_in[18];
    const float* ws  = (const float*)d_in[19];
    const float* bs  = (const float*)d_in[20];
    float* out = (float*)d_out;

    __half *A, *Hb, *W;
    cudaGetSymbolAddress((void**)&A,  g_A);
    cudaGetSymbolAddress((void**)&Hb, g_H);
    cudaGetSymbolAddress((void**)&W,  g_W);

    cudaFuncSetAttribute(gemm_mma<FF, HH>, cudaFuncAttributeMaxDynamicSharedMemorySize, GEMM_SMEM);
    cudaFuncSetAttribute(gemm_mma<HH, HH>, cudaFuncAttributeMaxDynamicSharedMemorySize, GEMM_SMEM);
    cudaFuncSetAttribute(gemm_mma<HH, OO>, cudaFuncAttributeMaxDynamicSharedMemorySize, GEMM_SMEM);

    __half* W0  = W + 0 * (size_t)(HH * HH);
    __half* W1t = W + 1 * (size_t)(HH * HH);
    __half* W2t = W + 2 * (size_t)(HH * HH);
    __half* W3t = W + 3 * (size_t)(HH * HH);

    const dim3 g2(HH / 128, MM / 256);   // (4, 304)
    const dim3 g1(OO / 128, MM / 256);   // (2, 304)

    // idx 0-2: setup needed by layer-1 GEMM
    cvt_w_kernel<<<(FF * HH + 255) / 256, 256>>>(W1, W0, FF, HH);                 // 0
    cvt_x_kernel<<<(MM * FF + 255) / 256, 256>>>(x, A, (size_t)MM * FF);          // 1
    cvt_w_kernel<<<(HH * HH + 255) / 256, 256>>>(W2, W1t, HH, HH);                // 2

    // idx 3: Layer 1 GEMM — ncu capture target
    gemm_mma<FF, HH><<<g2, 256, GEMM_SMEM>>>(A, W0, Hb);                           // 3

    cvt_w_kernel<<<(HH * HH + 255) / 256, 256>>>(W3, W2t, HH, HH);                // 4
    cvt_w_kernel<<<(HH * OO + 255) / 256, 256>>>(W4, W3t, HH, OO);                // 5
    gat_agg_h<HH, true><<<BB, HH>>>(Hb, ei, as1, ad1, b1, A);
    // Layer 2
    gemm_mma<HH, HH><<<g2, 256, GEMM_SMEM>>>(A, W1t, Hb);
    gat_agg_h<HH, true><<<BB, HH>>>(Hb, ei, as2, ad2, b2, A);
    // Layer 3
    gemm_mma<HH, HH><<<g2, 256, GEMM_SMEM>>>(A, W2t, Hb);
    gat_agg_h<HH, true><<<BB, HH>>>(Hb, ei, as3, ad3, b3, A);
    // Layer 4 + fused head
    gemm_mma<HH, OO><<<g1, 256, GEMM_SMEM>>>(A, W3t, Hb);
    gat_final<<<BB, OO>>>(Hb, ei, as4, ad4, b4, out, ws, bs);
}

// round 16
// speedup vs baseline: 1.0616x; 1.0161x over previous
#include <cuda_runtime.h>
#include <cuda_fp16.h>
#include <stdint.h>
#include <math.h>

// ---------------------------------------------------------------------------
// Problem constants
// ---------------------------------------------------------------------------
#define BB 4096
#define NN 19
#define EE 342
#define ET 361
#define FF 256
#define HH 512
#define OO 256
#define MM (BB * NN)      // 77824 = 304 * 256

// ---------------------------------------------------------------------------
// Scratch (device globals)
// ---------------------------------------------------------------------------
__device__ __half g_A [(size_t)MM * HH];     // activations fp16
__device__ __half g_H [(size_t)MM * HH];     // GEMM output fp16
__device__ __half g_W [4][HH * HH];          // transposed fp16 weights [N,K]

// ---------------------------------------------------------------------------
// Helpers
// ---------------------------------------------------------------------------
__device__ __forceinline__ uint32_t smem_u32(const void* p) {
    uint32_t a;
    asm("{ .reg .u64 t; cvta.to.shared.u64 t, %1; cvt.u32.u64 %0, t; }"
        : "=r"(a) : "l"(p));
    return a;
}
// 128-byte-row swizzle
#define SWZ(o) ((o) ^ (((o) >> 3) & 0x70))

__device__ __forceinline__ void cp16(uint32_t s, const void* g) {
    asm volatile("cp.async.cg.shared.global [%0], [%1], 16;" :: "r"(s), "l"(g));
}

__device__ __forceinline__ unsigned long long packf2(float x, float y) {
    unsigned long long u;
    asm("mov.b64 %0, {%1, %2};" : "=l"(u) : "f"(x), "f"(y));
    return u;
}
__device__ __forceinline__ float2 unpackf2(unsigned long long u) {
    float x, y;
    asm("mov.b64 {%0, %1}, %2;" : "=f"(x), "=f"(y) : "l"(u));
    return make_float2(x, y);
}
__device__ __forceinline__ void fma2(unsigned long long& acc,
                                     unsigned long long a, unsigned long long b) {
    asm("fma.rn.f32x2 %0, %1, %2, %0;" : "+l"(acc) : "l"(a), "l"(b));
}

// ---------------------------------------------------------------------------
// Setup kernels
// ---------------------------------------------------------------------------
__global__ void cvt_x_kernel(const float* __restrict__ x,
                             __half* __restrict__ A, size_t n) {
    size_t i = (size_t)blockIdx.x * 256 + threadIdx.x;
    if (i < n) A[i] = __float2half_rn(x[i]);
}

__global__ void cvt_w_kernel(const float* __restrict__ W,
                             __half* __restrict__ Wt, int K, int N) {
    int i = blockIdx.x * 256 + threadIdx.x;
    if (i < K * N) {
        int n = i / K, k = i % K;
        Wt[i] = __float2half_rn(W[(size_t)k * N + n]);
    }
}

// ---------------------------------------------------------------------------
// fp16 single-pass GEMM (unchanged from round 15)
// CTA tile 256x128, 8 warps (4M x 2N), warp tile 64x64, 3-stage cp.async.
// ---------------------------------------------------------------------------
#define GEMM_STAGE 49152
#define GEMM_SMEM  (3 * GEMM_STAGE)

template <int K, int NT>
__global__ void __launch_bounds__(256, 1)
gemm_mma(const __half* __restrict__ A, const __half* __restrict__ B,
         __half* __restrict__ Hout)
{
    extern __shared__ char smem[];
    const uint32_t sb = smem_u32(smem);
    const int tid  = threadIdx.x;
    const int wid  = tid >> 5;
    const int lane = tid & 31;
    const int bm = blockIdx.y * 256;
    const int bn = blockIdx.x * 128;
    const int wm = wid >> 1;
    const int wn = wid & 1;

    constexpr int NCH = K / 64;

    auto issue = [&](int ch) {
        const uint32_t st = sb + (uint32_t)(ch % 3) * GEMM_STAGE;
        const int kb = ch * 64;
#pragma unroll
        for (int i = 0; i < 12; i++) {
            int u = tid + i * 256;
            if (u < 2048) {
                int r = u >> 3, c = u & 7;
                cp16(st + SWZ((uint32_t)(r * 128 + c * 16)),
                     A + (size_t)(bm + r) * K + kb + c * 8);
            } else {
                int v = u - 2048;
                int r = v >> 3, c = v & 7;
                cp16(st + 32768u + SWZ((uint32_t)(r * 128 + c * 16)),
                     B + (size_t)(bn + r) * K + kb + c * 8);
            }
        }
    };

    float acc[4][8][4] = {};

    issue(0);
    asm volatile("cp.async.commit_group;" ::: "memory");
    issue(1);
    asm volatile("cp.async.commit_group;" ::: "memory");

    for (int ch = 0; ch < NCH; ch++) {
        if (ch + 2 < NCH) {
            asm volatile("cp.async.wait_group 1;" ::: "memory");
            __syncthreads();
            issue(ch + 2);
            asm volatile("cp.async.commit_group;" ::: "memory");
        } else if (ch + 1 < NCH) {
            asm volatile("cp.async.wait_group 1;" ::: "memory");
            __syncthreads();
        } else {
            asm volatile("cp.async.wait_group 0;" ::: "memory");
            __syncthreads();
        }

        const uint32_t st = sb + (uint32_t)(ch % 3) * GEMM_STAGE;
        const uint32_t sA = st;
        const uint32_t sB = st + 32768u;
#pragma unroll
        for (int kk = 0; kk < 4; kk++) {
            uint32_t b[16];
#pragma unroll
            for (int g = 0; g < 4; g++) {
                int n = wn * 64 + g * 16 + ((lane >> 4) * 8) + (lane & 7);
                int c = kk * 2 + ((lane >> 3) & 1);
                uint32_t so = SWZ((uint32_t)(n * 128 + c * 16));
                asm volatile(
                    "ldmatrix.sync.aligned.m8n8.x4.shared.b16 {%0,%1,%2,%3}, [%4];"
                    : "=r"(b[g * 4 + 0]), "=r"(b[g * 4 + 1]),
                      "=r"(b[g * 4 + 2]), "=r"(b[g * 4 + 3])
                    : "r"(sB + so));
            }
#pragma unroll
            for (int mt = 0; mt < 4; mt++) {
                uint32_t a[4];
                int m = wm * 64 + mt * 16 + (lane & 15);
                int c = kk * 2 + (lane >> 4);
                uint32_t so = SWZ((uint32_t)(m * 128 + c * 16));
                asm volatile(
                    "ldmatrix.sync.aligned.m8n8.x4.shared.b16 {%0,%1,%2,%3}, [%4];"
                    : "=r"(a[0]), "=r"(a[1]), "=r"(a[2]), "=r"(a[3])
                    : "r"(sA + so));
#pragma unroll
                for (int nt = 0; nt < 8; nt++) {
                    float* d = acc[mt][nt];
                    asm volatile(
                        "mma.sync.aligned.m16n8k16.row.col.f32.f16.f16.f32 "
                        "{%0,%1,%2,%3}, {%4,%5,%6,%7}, {%8,%9}, {%0,%1,%2,%3};"
                        : "+f"(d[0]), "+f"(d[1]), "+f"(d[2]), "+f"(d[3])
                        : "r"(a[0]), "r"(a[1]), "r"(a[2]), "r"(a[3]),
                          "r"(b[nt * 2]), "r"(b[nt * 2 + 1]));
                }
            }
        }
    }

#pragma unroll
    for (int mt = 0; mt < 4; mt++) {
        int row0 = bm + wm * 64 + mt * 16 + (lane >> 2);
#pragma unroll
        for (int nt = 0; nt < 8; nt++) {
            int col = bn + wn * 64 + nt * 8 + (lane & 3) * 2;
            float* d = acc[mt][nt];
            *(__half2*)(Hout + (size_t)row0 * NT + col) =
                __floats2half2_rn(d[0], d[1]);
            *(__half2*)(Hout + (size_t)(row0 + 8) * NT + col) =
                __floats2half2_rn(d[2], d[3]);
        }
    }
}

// ---------------------------------------------------------------------------
// Attention + aggregation. T = C/2 threads, 2 channels/thread.
// hs kept packed fp16 in smem (raw copy of H tile). Logits: warp-per-node
// over hs (R13 style). Agg loop: alpha duplicated float2 + fma.rn.f32x2.
// ---------------------------------------------------------------------------
template <int T>
__device__ __forceinline__ void alpha_edges(
    const int* __restrict__ ei, const float* als, const float* ald,
    float* nsum, float* ebuf, float* alphaM, int t)
{
    for (int e = t; e < ET; e += T) {
        int se = (e < EE) ? ei[e] : (e - EE);
        int de = (e < EE) ? ei[EE + e] : (e - EE);
        float z = als[se] + ald[de];
        float lg = (z >= 0.f) ? z : 0.2f * z;
        float ex = __expf(lg);
        ebuf[e] = ex;
        atomicAdd(&nsum[de], ex);
    }
    __syncthreads();
    if (t < NN) nsum[t] = 1.f / nsum[t];
    __syncthreads();
    for (int e = t; e < ET; e += T) {
        int se = (e < EE) ? ei[e] : (e - EE);
        int de = (e < EE) ? ei[EE + e] : (e - EE);
        atomicAdd(&alphaM[de * NN + se], ebuf[e] * nsum[de]);
    }
    __syncthreads();
}

// logits from packed-fp16 hs: warp per node
template <int T>
__device__ __forceinline__ void logits(
    const __half2* hs2, const float* __restrict__ a_s, const float* __restrict__ a_d,
    float* als, float* ald, int t)
{
    const float2* as2 = (const float2*)a_s;
    const float2* ad2 = (const float2*)a_d;
    const int w = t >> 5, lane = t & 31, NW = T / 32;
    for (int n = w; n < NN; n += NW) {
        float s = 0.f, d = 0.f;
#pragma unroll
        for (int j = 0; j < T / 32; j++) {
            int i = lane + 32 * j;
            float2 h = __half22float2(hs2[n * T + i]);
            float2 as = __ldg(as2 + i);
            float2 ad = __ldg(ad2 + i);
            s += h.x * as.x + h.y * as.y;
            d += h.x * ad.x + h.y * ad.y;
        }
#pragma unroll
        for (int o = 16; o; o >>= 1) {
            s += __shfl_xor_sync(0xffffffffu, s, o);
            d += __shfl_xor_sync(0xffffffffu, d, o);
        }
        if (lane == 0) { als[n] = s; ald[n] = d; }
    }
}

template <int C, bool RELU>
__global__ void __launch_bounds__(C / 2) gat_agg_h(
    const __half* __restrict__ H, const int* __restrict__ ei,
    const float* __restrict__ a_s, const float* __restrict__ a_d,
    const float* __restrict__ bias,
    __half* __restrict__ Oh)
{
    constexpr int T = C / 2;
    __shared__ alignas(16) __half2 hs2[NN * T];
    __shared__ float als[NN], ald[NN], nsum[NN];
    __shared__ float ebuf[ET];
    __shared__ float alphaM[NN * NN];
    __shared__ alignas(8) float2 alphaD[NN * NN];

    const int t = threadIdx.x;
    const size_t gbase = (size_t)blockIdx.x * NN * C;

    if (t < NN) nsum[t] = 0.f;
    for (int i = t; i < NN * NN; i += T) alphaM[i] = 0.f;
    {
        const uint4* H8 = (const uint4*)(H + gbase);
        uint4* s8 = (uint4*)hs2;
        for (int i = t; i < NN * C / 8; i += T) s8[i] = H8[i];
    }
    __syncthreads();

    logits<T>(hs2, a_s, a_d, als, ald, t);
    __syncthreads();

    alpha_edges<T>(ei, als, ald, nsum, ebuf, alphaM, t);

    // duplicate-pack alpha for LDS.64 broadcast
    for (int i = t; i < NN * NN; i += T) {
        float a = alphaM[i];
        alphaD[i] = make_float2(a, a);
    }

    // register-resident h (2 channels/thread, packed f32x2)
    unsigned long long h2[NN];
#pragma unroll
    for (int s = 0; s < NN; s++) {
        float2 f = __half22float2(hs2[s * T + t]);
        h2[s] = packf2(f.x, f.y);
    }
    __syncthreads();

    const float2 bcf = __ldg(((const float2*)bias) + t);
    const unsigned long long bc = packf2(bcf.x, bcf.y);
    __half2* O2 = (__half2*)(Oh + gbase);
#pragma unroll
    for (int n = 0; n < NN; n++) {
        unsigned long long acc = bc;
        const unsigned long long* ap = (const unsigned long long*)&alphaD[n * NN];
#pragma unroll
        for (int s = 0; s < NN; s++) fma2(acc, ap[s], h2[s]);
        float2 v = unpackf2(acc);
        if (RELU) { v.x = fmaxf(v.x, 0.f); v.y = fmaxf(v.y, 0.f); }
        O2[(size_t)n * T + t] = __floats2half2_rn(v.x, v.y);
    }
}

// Final layer: aggregation (no relu) + fused head, register-resident v.
__global__ void __launch_bounds__(OO / 2) gat_final(
    const __half* __restrict__ H, const int* __restrict__ ei,
    const float* __restrict__ a_s, const float* __restrict__ a_d,
    const float* __restrict__ bias, float* __restrict__ outp,
    const float* __restrict__ ws, const float* __restrict__ bsc)
{
    constexpr int C = OO;
    constexpr int T = C / 2;
    __shared__ alignas(16) __half2 hs2[NN * T];
    __shared__ float als[NN], ald[NN], nsum[NN];
    __shared__ float ebuf[ET];
    __shared__ float alphaM[NN * NN];
    __shared__ alignas(8) float2 alphaD[NN * NN];
    __shared__ float sbuf[NN];

    const int t = threadIdx.x;
    const int lane = t & 31;
    const size_t gbase = (size_t)blockIdx.x * NN * C;

    if (t < NN) { nsum[t] = 0.f; sbuf[t] = 0.f; }
    for (int i = t; i < NN * NN; i += T) alphaM[i] = 0.f;
    {
        const uint4* H8 = (const uint4*)(H + gbase);
        uint4* s8 = (uint4*)hs2;
        for (int i = t; i < NN * C / 8; i += T) s8[i] = H8[i];
    }
    __syncthreads();

    logits<T>(hs2, a_s, a_d, als, ald, t);
    __syncthreads();

    alpha_edges<T>(ei, als, ald, nsum, ebuf, alphaM, t);

    for (int i = t; i < NN * NN; i += T) {
        float a = alphaM[i];
        alphaD[i] = make_float2(a, a);
    }

    unsigned long long h2[NN];
#pragma unroll
    for (int s = 0; s < NN; s++) {
        float2 f = __half22float2(hs2[s * T + t]);
        h2[s] = packf2(f.x, f.y);
    }
    __syncthreads();

    const float2 bcf = __ldg(((const float2*)bias) + t);
    const unsigned long long bc = packf2(bcf.x, bcf.y);
    float2 v[NN];
#pragma unroll
    for (int n = 0; n < NN; n++) {
        unsigned long long acc = bc;
        const unsigned long long* ap = (const unsigned long long*)&alphaD[n * NN];
#pragma unroll
        for (int s = 0; s < NN; s++) fma2(acc, ap[s], h2[s]);
        v[n] = unpackf2(acc);
    }

    // p = sum_n ws[n] * v[n] (per-thread 2 channels)
    float2 p = make_float2(0.f, 0.f);
#pragma unroll
    for (int n = 0; n < NN; n++) {
        float w = __ldg(ws + n);
        p.x += w * v[n].x;
        p.y += w * v[n].y;
    }

    // scores: warp reduce + smem atomic
#pragma unroll
    for (int n = 0; n < NN; n++) {
        float s = v[n].x * p.x + v[n].y * p.y;
#pragma unroll
        for (int o = 16; o; o >>= 1) s += __shfl_xor_sync(0xffffffffu, s, o);
        if (lane == 0) atomicAdd(&sbuf[n], s);
    }
    __syncthreads();
    if (t < NN)
        outp[(size_t)blockIdx.x * NN + t] = 1.f / (1.f + __expf(-(sbuf[t] + bsc[0])));
}

// ---------------------------------------------------------------------------
// Launch.  ncu captures launch index 3 -> first gat_agg placed there.
// ---------------------------------------------------------------------------
extern "C" void kernel_launch(void* const* d_in, const int* in_sizes, int n_in,
                              void* d_out, int out_size)
{
    (void)in_sizes; (void)n_in; (void)out_size;
    const float* x   = (const float*)d_in[0];
    const int*   ei  = (const int*)  d_in[1];
    const float* W1  = (const float*)d_in[3];
    const float* as1 = (const float*)d_in[4];
    const float* ad1 = (const float*)d_in[5];
    const float* b1  = (const float*)d_in[6];
    const float* W2  = (const float*)d_in[7];
    const float* as2 = (const float*)d_in[8];
    const float* ad2 = (const float*)d_in[9];
    const float* b2  = (const float*)d_in[10];
    const float* W3  = (const float*)d_in[11];
    const float* as3 = (const float*)d_in[12];
    const float* ad3 = (const float*)d_in[13];
    const float* b3  = (const float*)d_in[14];
    const float* W4  = (const float*)d_in[15];
    const float* as4 = (const float*)d_in[16];
    const float* ad4 = (const float*)d_in[17];
    const float* b4  = (const float*)d_in[18];
    const float* ws  = (const float*)d_in[19];
    const float* bs  = (const float*)d_in[20];
    float* out = (float*)d_out;

    __half *A, *Hb, *W;
    cudaGetSymbolAddress((void**)&A,  g_A);
    cudaGetSymbolAddress((void**)&Hb, g_H);
    cudaGetSymbolAddress((void**)&W,  g_W);

    cudaFuncSetAttribute(gemm_mma<FF, HH>, cudaFuncAttributeMaxDynamicSharedMemorySize, GEMM_SMEM);
    cudaFuncSetAttribute(gemm_mma<HH, HH>, cudaFuncAttributeMaxDynamicSharedMemorySize, GEMM_SMEM);
    cudaFuncSetAttribute(gemm_mma<HH, OO>, cudaFuncAttributeMaxDynamicSharedMemorySize, GEMM_SMEM);

    __half* W0  = W + 0 * (size_t)(HH * HH);
    __half* W1t = W + 1 * (size_t)(HH * HH);
    __half* W2t = W + 2 * (size_t)(HH * HH);
    __half* W3t = W + 3 * (size_t)(HH * HH);

    const dim3 g2(HH / 128, MM / 256);   // (4, 304)
    const dim3 g1(OO / 128, MM / 256);   // (2, 304)

    // idx 0-1: setup needed by layer-1 GEMM
    cvt_w_kernel<<<(FF * HH + 255) / 256, 256>>>(W1, W0, FF, HH);                 // 0
    cvt_x_kernel<<<(MM * FF + 255) / 256, 256>>>(x, A, (size_t)MM * FF);          // 1

    // idx 2: Layer 1 GEMM
    gemm_mma<FF, HH><<<g2, 256, GEMM_SMEM>>>(A, W0, Hb);                           // 2
    // idx 3: Layer 1 aggregation — ncu capture target
    gat_agg_h<HH, true><<<BB, HH / 2>>>(Hb, ei, as1, ad1, b1, A);                  // 3

    cvt_w_kernel<<<(HH * HH + 255) / 256, 256>>>(W2, W1t, HH, HH);                // 4
    cvt_w_kernel<<<(HH * HH + 255) / 256, 256>>>(W3, W2t, HH, HH);                // 5
    cvt_w_kernel<<<(HH * OO + 255) / 256, 256>>>(W4, W3t, HH, OO);                // 6

    // Layer 2
    gemm_mma<HH, HH><<<g2, 256, GEMM_SMEM>>>(A, W1t, Hb);
    gat_agg_h<HH, true><<<BB, HH / 2>>>(Hb, ei, as2, ad2, b2, A);
    // Layer 3
    gemm_mma<HH, HH><<<g2, 256, GEMM_SMEM>>>(A, W2t, Hb);
    gat_agg_h<HH, true><<<BB, HH / 2>>>(Hb, ei, as3, ad3, b3, A);
    // Layer 4 + fused head
    gemm_mma<HH, OO><<<g1, 256, GEMM_SMEM>>>(A, W3t, Hb);
    gat_final<<<BB, OO / 2>>>(Hb, ei, as4, ad4, b4, out, ws, bs);
}